// round 16
// baseline (speedup 1.0000x reference)
#include <cuda_runtime.h>
#include <math.h>
#include <stdint.h>

#define PI_F 3.14159265358979323846f

// Precomputed constants: [0:64) fused U gates (8 gates x 4 entries x float2),
// [64:80) W_enc rows 512..515, [80:96) W_out, [96:100) b_enc, [100:104) b_out.
__device__ float gSetup[128];

__device__ __forceinline__ float2 cmul(float2 a, float2 b) {
    return make_float2(a.x*b.x - a.y*b.y, a.x*b.y + a.y*b.x);
}
// tanh via exp: abs err ~1e-7 (validated R13-R15, rel_err 7.9e-7).
__device__ __forceinline__ float tanh_fast(float x) {
    float e = __expf(2.0f * x);
    return 1.0f - 2.0f / (e + 1.0f);
}

#define GATE_PAIR(a, b, u00, u01, u10, u11) do { \
    float2 ta = (a), tb = (b); \
    (a).x = (u00).x*ta.x - (u00).y*ta.y + (u01).x*tb.x - (u01).y*tb.y; \
    (a).y = (u00).x*ta.y + (u00).y*ta.x + (u01).x*tb.y + (u01).y*tb.x; \
    (b).x = (u10).x*ta.x - (u10).y*ta.y + (u11).x*tb.x - (u11).y*tb.y; \
    (b).y = (u10).x*ta.y + (u10).y*ta.x + (u11).x*tb.y + (u11).y*tb.x; \
} while (0)

// ============== setup kernel: 1 block, 64 threads, runs once ================
__global__ void qrnn_setup_kernel(const float* __restrict__ W_enc,
                                  const float* __restrict__ b_enc,
                                  const float* __restrict__ theta,
                                  const float* __restrict__ W_out,
                                  const float* __restrict__ b_out)
{
    int tid = threadIdx.x;
    if (tid < 8) {
        const float* th = theta + tid * 3;   // (l*4+q) flattened == gate index
        float ca, sa, cb, sb, cy, sy;
        sincosf(0.5f * th[0], &sa, &ca);
        sincosf(0.5f * th[1], &sb, &cb);
        sincosf(0.5f * th[2], &sy, &cy);
        float2 RX0 = make_float2(ca, 0.f),  RX1 = make_float2(0.f, -sa);
        float2 RX2 = make_float2(0.f, -sa), RX3 = make_float2(ca, 0.f);
        float2 RZ0 = make_float2(cb, -sb),  RZ3 = make_float2(cb, sb);
        float2 M0 = cmul(RZ0, RX0);
        float2 M1 = cmul(RZ0, RX1);
        float2 M2 = cmul(RZ3, RX2);
        float2 M3 = cmul(RZ3, RX3);
        float2 U[4];
        U[0] = make_float2(cy*M0.x - sy*M2.x, cy*M0.y - sy*M2.y);
        U[1] = make_float2(cy*M1.x - sy*M3.x, cy*M1.y - sy*M3.y);
        U[2] = make_float2(sy*M0.x + cy*M2.x, sy*M0.y + cy*M2.y);
        U[3] = make_float2(sy*M1.x + cy*M3.x, sy*M1.y + cy*M3.y);
        #pragma unroll
        for (int k = 0; k < 4; k++) {
            gSetup[(tid * 4 + k) * 2]     = U[k].x;
            gSetup[(tid * 4 + k) * 2 + 1] = U[k].y;
        }
    }
    if (tid >= 8  && tid < 24) gSetup[64  + tid - 8]  = W_enc[2048 + (tid - 8)];
    if (tid >= 24 && tid < 40) gSetup[80  + tid - 24] = W_out[tid - 24];
    if (tid >= 40 && tid < 44) gSetup[96  + tid - 40] = b_enc[tid - 40];
    if (tid >= 44 && tid < 48) gSetup[100 + tid - 44] = b_out[tid - 44];
}

// ============== fused kernel: GEMV + per-warp circuit tail ==================
// 256 threads, 16 rows/block. Warp w: GEMV for rows 2w,2w+1 (identical to the
// measured-10.6us design), then lanes 0..3 simulate those 2 rows (2 threads
// per row, partner shfl_xor 1). No sincosf head, no block-wide tail barrier.
__global__ __launch_bounds__(256, 4)
void qrnn_fused2_kernel(const float* __restrict__ inputs,   // (B, 512)
                        const float* __restrict__ prev_h,   // (B, 4)
                        const float* __restrict__ W_enc,    // (516, 4)
                        float* __restrict__ out,            // (B, 4)
                        int B)
{
    __shared__ float4 sW[512];
    __shared__ float  sSetup[104];
    __shared__ float  sPre[16][4];

    const int tid  = threadIdx.x;
    const int lane = tid & 31;
    const int wid  = tid >> 5;
    const long rowbase = (long)blockIdx.x * 16;

    // ---- smem fills: pure copies, no compute chain --------------------------
    const float4* w4g = reinterpret_cast<const float4*>(W_enc);
    sW[tid]       = w4g[tid];
    sW[tid + 256] = w4g[tid + 256];
    if (tid < 104) sSetup[tid] = gSetup[tid];

    // ---- early prev_h prefetch for this warp's tail rows --------------------
    float4 ph = make_float4(0.f, 0.f, 0.f, 0.f);
    if (lane < 4) {
        long prow = rowbase + 2 * wid + (lane >> 1);
        if (prow >= B) prow = B - 1;
        ph = reinterpret_cast<const float4*>(prev_h)[prow];
    }
    __syncthreads();

    // ================= GEMV (2 rows per warp) — unchanged ====================
    long r0 = rowbase + wid * 2;
    if (r0 + 2 > B) r0 = (B >= 2) ? (long)(B - 2) : 0;
    const float* p0 = inputs + r0 * 512 + lane;

    float xa[16], xb[16];
    #pragma unroll
    for (int m = 0; m < 16; m++) xa[m] = p0[32 * m];
    #pragma unroll
    for (int m = 0; m < 16; m++) xb[m] = p0[512 + 32 * m];

    float a0 = 0.f, a1 = 0.f, a2 = 0.f, a3 = 0.f;
    float b0 = 0.f, b1 = 0.f, b2 = 0.f, b3 = 0.f;
    #pragma unroll
    for (int m = 0; m < 16; m++) {
        float4 w = sW[lane + 32 * m];
        a0 = fmaf(xa[m], w.x, a0);
        a1 = fmaf(xa[m], w.y, a1);
        a2 = fmaf(xa[m], w.z, a2);
        a3 = fmaf(xa[m], w.w, a3);
        b0 = fmaf(xb[m], w.x, b0);
        b1 = fmaf(xb[m], w.y, b1);
        b2 = fmaf(xb[m], w.z, b2);
        b3 = fmaf(xb[m], w.w, b3);
    }

    const bool p1b = lane & 1, p2b = lane & 2;
    {
        float v01 = p1b ? a1 : a0, o01 = p1b ? a0 : a1;
        v01 += __shfl_xor_sync(0xffffffffu, o01, 1);
        float v23 = p1b ? a3 : a2, o23 = p1b ? a2 : a3;
        v23 += __shfl_xor_sync(0xffffffffu, o23, 1);
        float v = p2b ? v23 : v01, o = p2b ? v01 : v23;
        v += __shfl_xor_sync(0xffffffffu, o, 2);
        v += __shfl_xor_sync(0xffffffffu, v, 4);
        v += __shfl_xor_sync(0xffffffffu, v, 8);
        v += __shfl_xor_sync(0xffffffffu, v, 16);
        a0 = v;
    }
    {
        float v01 = p1b ? b1 : b0, o01 = p1b ? b0 : b1;
        v01 += __shfl_xor_sync(0xffffffffu, o01, 1);
        float v23 = p1b ? b3 : b2, o23 = p1b ? b2 : b3;
        v23 += __shfl_xor_sync(0xffffffffu, o23, 1);
        float v = p2b ? v23 : v01, o = p2b ? v01 : v23;
        v += __shfl_xor_sync(0xffffffffu, o, 2);
        v += __shfl_xor_sync(0xffffffffu, v, 4);
        v += __shfl_xor_sync(0xffffffffu, v, 8);
        v += __shfl_xor_sync(0xffffffffu, v, 16);
        b0 = v;
    }
    if (lane < 4)       sPre[2 * wid][lane] = a0;
    else if (lane < 8)  sPre[2 * wid + 1][lane & 3] = b0;
    __syncwarp();   // warp-private handoff; no block barrier

    // ================= per-warp circuit tail (lanes 0..3) ====================
    if (lane < 4) {
        const float2* sU2    = reinterpret_cast<const float2*>(sSetup);
        const float*  sWtail = sSetup + 64;
        const float*  sWout  = sSetup + 80;
        const float*  sbenc  = sSetup + 96;
        const float*  sbout  = sSetup + 100;
        const unsigned mask  = 0xFu;

        const int  sub = lane & 1;
        const int  lr  = 2 * wid + (lane >> 1);
        const long row = rowbase + lr;

        float acc[4];
        #pragma unroll
        for (int j = 0; j < 4; j++) {
            acc[j] = sPre[lr][j] + sbenc[j]
                   + ph.x * sWtail[j]     + ph.y * sWtail[4 + j]
                   + ph.z * sWtail[8 + j] + ph.w * sWtail[12 + j];
        }

        // layer-0 folding: wv[q] = U_{0,q} * RY(angle_q)|0>
        float2 wv[4][2];
        #pragma unroll
        for (int q = 0; q < 4; q++) {
            float half = tanh_fast(acc[q]) * (0.5f * PI_F);
            float c, s;
            __sincosf(half, &s, &c);
            float2 u00 = sU2[q*4+0], u01 = sU2[q*4+1];
            float2 u10 = sU2[q*4+2], u11 = sU2[q*4+3];
            wv[q][0] = make_float2(c*u00.x + s*u01.x, c*u00.y + s*u01.y);
            wv[q][1] = make_float2(c*u10.x + s*u11.x, c*u10.y + s*u11.y);
        }
        // tensor expansion of OWN amplitudes: i = sub*8 + j (j = b2 b1 b0)
        float2 pre01[2], p23[4];
        pre01[0] = cmul(wv[0][sub], wv[1][0]);
        pre01[1] = cmul(wv[0][sub], wv[1][1]);
        #pragma unroll
        for (int b1 = 0; b1 < 2; b1++)
            #pragma unroll
            for (int bb = 0; bb < 2; bb++)
                p23[b1*2+bb] = cmul(wv[2][b1], wv[3][bb]);
        float2 A[8];
        #pragma unroll
        for (int j = 0; j < 8; j++)
            A[j] = cmul(pre01[j >> 2], p23[j & 3]);

        // layer-0 CNOT chain
        #pragma unroll
        for (int j = 0; j < 4; j++) {
            float2 lo = A[j], hi = A[j + 4];
            A[j]     = sub ? hi : lo;
            A[j + 4] = sub ? lo : hi;
        }
        { float2 t = A[4]; A[4] = A[6]; A[6] = t; }
        { float2 t = A[5]; A[5] = A[7]; A[7] = t; }
        { float2 t = A[2]; A[2] = A[3]; A[3] = t; }
        { float2 t = A[6]; A[6] = A[7]; A[7] = t; }

        // layer-1 q0 gate: partner thread via shfl_xor 1
        {
            float2 u00 = sU2[16], u01 = sU2[17], u10 = sU2[18], u11 = sU2[19];
            float2 ua = sub ? u10 : u00;
            float2 ub = sub ? u11 : u01;
            #pragma unroll
            for (int j = 0; j < 8; j++) {
                float2 o;
                o.x = __shfl_xor_sync(mask, A[j].x, 1);
                o.y = __shfl_xor_sync(mask, A[j].y, 1);
                float2 x = sub ? o : A[j];
                float2 y = sub ? A[j] : o;
                A[j].x = ua.x*x.x - ua.y*x.y + ub.x*y.x - ub.y*y.y;
                A[j].y = ua.x*x.y + ua.y*x.x + ub.x*y.y + ub.y*y.x;
            }
        }
        // layer-1 q1..q3 gates: local pairs
        {
            float2 u00 = sU2[20], u01 = sU2[21], u10 = sU2[22], u11 = sU2[23];
            #pragma unroll
            for (int j = 0; j < 4; j++) GATE_PAIR(A[j], A[j+4], u00, u01, u10, u11);
        }
        {
            float2 u00 = sU2[24], u01 = sU2[25], u10 = sU2[26], u11 = sU2[27];
            GATE_PAIR(A[0], A[2], u00, u01, u10, u11);
            GATE_PAIR(A[1], A[3], u00, u01, u10, u11);
            GATE_PAIR(A[4], A[6], u00, u01, u10, u11);
            GATE_PAIR(A[5], A[7], u00, u01, u10, u11);
        }
        {
            float2 u00 = sU2[28], u01 = sU2[29], u10 = sU2[30], u11 = sU2[31];
            GATE_PAIR(A[0], A[1], u00, u01, u10, u11);
            GATE_PAIR(A[2], A[3], u00, u01, u10, u11);
            GATE_PAIR(A[4], A[5], u00, u01, u10, u11);
            GATE_PAIR(A[6], A[7], u00, u01, u10, u11);
        }

        // layer-1 CNOT chain
        #pragma unroll
        for (int j = 0; j < 4; j++) {
            float2 lo = A[j], hi = A[j + 4];
            A[j]     = sub ? hi : lo;
            A[j + 4] = sub ? lo : hi;
        }
        { float2 t = A[4]; A[4] = A[6]; A[6] = t; }
        { float2 t = A[5]; A[5] = A[7]; A[7] = t; }
        { float2 t = A[2]; A[2] = A[3]; A[3] = t; }
        { float2 t = A[6]; A[6] = A[7]; A[7] = t; }

        // PauliZ expectations
        float p[8];
        #pragma unroll
        for (int j = 0; j < 8; j++) p[j] = A[j].x*A[j].x + A[j].y*A[j].y;
        float s  = p[0]+p[1]+p[2]+p[3]+p[4]+p[5]+p[6]+p[7];
        float e0 = sub ? -s : s;
        float e1 = (p[0]+p[1]+p[2]+p[3]) - (p[4]+p[5]+p[6]+p[7]);
        float e2 = (p[0]+p[1]+p[4]+p[5]) - (p[2]+p[3]+p[6]+p[7]);
        float e3 = (p[0]+p[2]+p[4]+p[6]) - (p[1]+p[3]+p[5]+p[7]);
        e0 += __shfl_xor_sync(mask, e0, 1);
        e1 += __shfl_xor_sync(mask, e1, 1);
        e2 += __shfl_xor_sync(mask, e2, 1);
        e3 += __shfl_xor_sync(mask, e3, 1);

        const int c0 = sub * 2;
        float oc0 = tanh_fast(e0*sWout[c0]   + e1*sWout[4+c0] + e2*sWout[8+c0] + e3*sWout[12+c0] + sbout[c0]);
        float oc1 = tanh_fast(e0*sWout[c0+1] + e1*sWout[5+c0] + e2*sWout[9+c0] + e3*sWout[13+c0] + sbout[c0+1]);
        if (row < B)
            reinterpret_cast<float2*>(out)[row * 2 + sub] = make_float2(oc0, oc1);
    }
}

extern "C" void kernel_launch(void* const* d_in, const int* in_sizes, int n_in,
                              void* d_out, int out_size)
{
    const float* inputs = (const float*)d_in[0];
    const float* prev_h = (const float*)d_in[1];
    const float* W_enc  = (const float*)d_in[2];
    const float* b_enc  = (const float*)d_in[3];
    const float* theta  = (const float*)d_in[4];
    const float* W_out  = (const float*)d_in[5];
    const float* b_out  = (const float*)d_in[6];

    int B = in_sizes[0] / 512;

    qrnn_setup_kernel<<<1, 64>>>(W_enc, b_enc, theta, W_out, b_out);

    int grid = (B + 15) / 16;
    qrnn_fused2_kernel<<<grid, 256>>>(inputs, prev_h, W_enc, (float*)d_out, B);
}